// round 4
// baseline (speedup 1.0000x reference)
#include <cuda_runtime.h>
#include <math.h>

#define CN 64
#define CC 64
#define CT 300
#define CV 25
#define TVN 7500
#define ICN 16
#define EPSBN 1e-5f

static const int OFF_FA = 0;          // 23,040,000
static const int OFF_FB = 23040000;   // 23,040,000
static const int OFF_S  = 46080000;   // 120,000
static const int OFF_Z  = 46200000;   // 92,160,000  (later reused for yt)
static const int OFF_YG = 138360000;  // 30,720,000
static const int OFF_W  = 169080000;  // transposed weights: WabT(6144), WdT(12288), WtT(36864)
// y2 reuses [0, 30.72M) (fa/fb dead after k_S)

__device__ float g_scratch[169140000];
__device__ float g_partsum[1024];
__device__ float g_partss[1024];
__device__ float g_bnA[64];
__device__ float g_bnB[64];

// ---------------------------------------------------------------------------
// K0: transpose weights for coalesced tile loads
//  WabT[c*96+row] = row<48 ? Wa[row*64+c] : Wb[(row-48)*64+c]
//  WdT[kc*64+o]   = Wd[k*4096 + o*64 + c]        (kc = k*64+c, 192x64)
//  WtT[cdt*64+o]  = Wt[o*576 + cdt]              (576x64)
// ---------------------------------------------------------------------------
__global__ void k_prep(const float* __restrict__ Wa, const float* __restrict__ Wb,
                       const float* __restrict__ Wd, const float* __restrict__ Wt,
                       float* __restrict__ wout) {
  int idx = blockIdx.x * 256 + threadIdx.x;
  if (idx < 6144) {
    int c = idx / 96, row = idx - c * 96;
    wout[idx] = (row < 48) ? Wa[row * 64 + c] : Wb[(row - 48) * 64 + c];
  } else if (idx < 6144 + 12288) {
    int j = idx - 6144;
    int o = j & 63, kc = j >> 6;
    int k = kc >> 6, c = kc & 63;
    wout[idx] = Wd[k * 4096 + o * 64 + c];
  } else if (idx < 55296) {
    int j = idx - 18432;
    int o = j & 63, cdt = j >> 6;
    wout[idx] = Wt[o * 576 + cdt];
  }
}

// ---------------------------------------------------------------------------
// K1: fa/fb 1x1 convs: GEMM 96rows x 64k x 128cols per block
// ---------------------------------------------------------------------------
__global__ __launch_bounds__(384) void k_fafb(
    const float* __restrict__ x, const float* __restrict__ wabT,
    const float* __restrict__ ba, const float* __restrict__ bb,
    float* __restrict__ fa, float* __restrict__ fb) {
  __shared__ __align__(16) float WS[64 * 96];
  __shared__ __align__(16) float xs[64 * 128];
  int n = blockIdx.y, col0 = blockIdx.x * 128;
  int tid = threadIdx.x;
  for (int m = tid; m < 6144; m += 384) WS[m] = wabT[m];
  const float* xp = x + n * (CC * TVN);
  for (int m = tid; m < 8192; m += 384) {
    int c = m >> 7, col = m & 127;
    int g = col0 + col;
    xs[m] = (g < TVN) ? xp[c * TVN + g] : 0.f;
  }
  __syncthreads();
  int ty = tid >> 4, tx = tid & 15;  // 24 x 16
  float acc[4][8];
#pragma unroll
  for (int r = 0; r < 4; r++)
#pragma unroll
    for (int j = 0; j < 8; j++) acc[r][j] = 0.f;
#pragma unroll 4
  for (int k = 0; k < 64; k++) {
    float4 wr = *(const float4*)&WS[k * 96 + ty * 4];
    float4 xa = *(const float4*)&xs[k * 128 + tx * 8];
    float4 xb = *(const float4*)&xs[k * 128 + tx * 8 + 4];
    float w[4] = {wr.x, wr.y, wr.z, wr.w};
    float xv[8] = {xa.x, xa.y, xa.z, xa.w, xb.x, xb.y, xb.z, xb.w};
#pragma unroll
    for (int r = 0; r < 4; r++)
#pragma unroll
      for (int j = 0; j < 8; j++) acc[r][j] += w[r] * xv[j];
  }
  bool fast = (col0 + 128 <= TVN);
#pragma unroll
  for (int r = 0; r < 4; r++) {
    int row = ty * 4 + r;
    int rr = (row < 48) ? row : row - 48;
    float* outp = (row < 48) ? fa : fb;
    float bias = (row < 48) ? ba[rr] : bb[rr];
    int k = rr >> 4, i = rr & 15;
    int base = (k * CN + n) * (ICN * TVN) + i * TVN + col0 + tx * 8;
    if (fast) {
      float4 o1 = make_float4(acc[r][0] + bias, acc[r][1] + bias, acc[r][2] + bias, acc[r][3] + bias);
      float4 o2 = make_float4(acc[r][4] + bias, acc[r][5] + bias, acc[r][6] + bias, acc[r][7] + bias);
      *(float4*)&outp[base] = o1;
      *(float4*)&outp[base + 4] = o2;
    } else {
#pragma unroll
      for (int j = 0; j < 8; j++)
        if (col0 + tx * 8 + j < TVN) outp[base + j] = acc[r][j] + bias;
    }
  }
}

// ---------------------------------------------------------------------------
// K2: S[k,n,v,w] = (1/4800) sum fa*fb; softmax over v; + (adj+PA)
// ---------------------------------------------------------------------------
__global__ __launch_bounds__(224) void k_S(
    const float* __restrict__ adj, const float* __restrict__ PA,
    const float* __restrict__ fa, const float* __restrict__ fb,
    float* __restrict__ Sout) {
  int k = blockIdx.x, n = blockIdx.y;
  __shared__ float sfa[1600], sfb[1600];
  __shared__ float sP[8 * 625];
  __shared__ float sS[625];
  __shared__ float smx[25], sinv[25];
  const float* fap = fa + (k * CN + n) * (ICN * TVN);
  const float* fbp = fb + (k * CN + n) * (ICN * TVN);
  int tid = threadIdx.x;
  float acc[25];
#pragma unroll
  for (int q = 0; q < 25; q++) acc[q] = 0.f;
  int tile = tid % 25, es = tid / 25;
  int vt = (tile / 5) * 5, wt = (tile % 5) * 5;
  for (int ch = 0; ch < 75; ch++) {
    __syncthreads();
    int d0 = ch * 64;
    for (int m = tid; m < 1600; m += 224) {
      int e = m / 25, vv = m - e * 25;
      int d = d0 + e;
      int i = d / 300, t = d - i * 300;
      int addr = i * TVN + t * 25 + vv;
      sfa[m] = fap[addr];
      sfb[m] = fbp[addr];
    }
    __syncthreads();
    if (tid < 200) {
#pragma unroll
      for (int ee = 0; ee < 8; ee++) {
        int e = es * 8 + ee;
        float av[5], bv[5];
#pragma unroll
        for (int q = 0; q < 5; q++) { av[q] = sfa[e * 25 + vt + q]; bv[q] = sfb[e * 25 + wt + q]; }
#pragma unroll
        for (int a2 = 0; a2 < 5; a2++)
#pragma unroll
          for (int b2 = 0; b2 < 5; b2++) acc[a2 * 5 + b2] += av[a2] * bv[b2];
      }
    }
  }
  __syncthreads();
  if (tid < 200) {
#pragma unroll
    for (int a2 = 0; a2 < 5; a2++)
#pragma unroll
      for (int b2 = 0; b2 < 5; b2++)
        sP[es * 625 + (vt + a2) * 25 + (wt + b2)] = acc[a2 * 5 + b2];
  }
  __syncthreads();
  for (int m = tid; m < 625; m += 224) {
    float s = 0.f;
#pragma unroll
    for (int e = 0; e < 8; e++) s += sP[e * 625 + m];
    sS[m] = s * (1.0f / 4800.0f);
  }
  __syncthreads();
  if (tid < 25) {
    float mx = -1e30f;
    for (int v = 0; v < 25; v++) mx = fmaxf(mx, sS[v * 25 + tid]);
    float sm = 0.f;
    for (int v = 0; v < 25; v++) sm += expf(sS[v * 25 + tid] - mx);
    smx[tid] = mx;
    sinv[tid] = 1.f / sm;
  }
  __syncthreads();
  float* so = Sout + (k * CN + n) * 625;
  for (int m = tid; m < 625; m += 224) {
    int w = m % 25;
    so[m] = expf(sS[m] - smx[w]) * sinv[w] + adj[k * 625 + m] + PA[k * 625 + m];
  }
}

// ---------------------------------------------------------------------------
// K3: Z[k,n,c,t,w] = sum_v x[n,c,t,v] * S[k,n,v,w]
// ---------------------------------------------------------------------------
__global__ __launch_bounds__(256) void k_Z(
    const float* __restrict__ x, const float* __restrict__ Sbuf,
    float* __restrict__ Z) {
  int n = blockIdx.y, t0 = blockIdx.x * 6;
  __shared__ float Ss[1875];
  __shared__ float xs[64 * 150];
  int tid = threadIdx.x;
  for (int m = tid; m < 1875; m += 256) {
    int k = m / 625;
    Ss[m] = Sbuf[(k * CN + n) * 625 + (m - k * 625)];
  }
  const float* xp = x + n * (CC * TVN) + t0 * 25;
  for (int m = tid; m < 64 * 150; m += 256) {
    int c = m / 150, col = m - c * 150;
    xs[m] = xp[c * TVN + col];
  }
  __syncthreads();
  for (int tsk = tid; tsk < 720; tsk += 256) {
    int k = tsk / 240, r = tsk - k * 240;
    int cg = r / 30;
    int r2 = r - cg * 30;
    int tt = r2 / 5, wt = r2 - tt * 5;
    int cb = cg * 8, w0 = wt * 5;
    const float* sp = Ss + k * 625;
    float acc[8][5];
#pragma unroll
    for (int a2 = 0; a2 < 8; a2++)
#pragma unroll
      for (int b2 = 0; b2 < 5; b2++) acc[a2][b2] = 0.f;
    for (int v = 0; v < 25; v++) {
      float xv[8], sv[5];
#pragma unroll
      for (int ci = 0; ci < 8; ci++) xv[ci] = xs[(cb + ci) * 150 + tt * 25 + v];
#pragma unroll
      for (int wi = 0; wi < 5; wi++) sv[wi] = sp[v * 25 + w0 + wi];
#pragma unroll
      for (int ci = 0; ci < 8; ci++)
#pragma unroll
        for (int wi = 0; wi < 5; wi++) acc[ci][wi] += xv[ci] * sv[wi];
    }
#pragma unroll
    for (int ci = 0; ci < 8; ci++) {
      int base = ((k * CN + n) * CC + cb + ci) * TVN + (t0 + tt) * 25 + w0;
#pragma unroll
      for (int wi = 0; wi < 5; wi++) Z[base + wi] = acc[ci][wi];
    }
  }
}

// ---------------------------------------------------------------------------
// K4: y1[n,o,col] = sum_{kc<192} WdT[kc][o] * Z[kc][col], 64x128 tile
// ---------------------------------------------------------------------------
__global__ __launch_bounds__(256) void k_yg(
    const float* __restrict__ Z, const float* __restrict__ wdT,
    float* __restrict__ y1) {
  __shared__ __align__(16) float Ws[32 * 64];
  __shared__ __align__(16) float Zs[32 * 128];
  int n = blockIdx.y, col0 = blockIdx.x * 128;
  int tid = threadIdx.x;
  int ty = tid >> 4, tx = tid & 15;  // 16 x 16
  float acc[4][8];
#pragma unroll
  for (int r = 0; r < 4; r++)
#pragma unroll
    for (int j = 0; j < 8; j++) acc[r][j] = 0.f;
  for (int ch = 0; ch < 6; ch++) {
    __syncthreads();
    int kc0 = ch * 32;
    for (int m = tid; m < 2048; m += 256) Ws[m] = wdT[kc0 * 64 + m];
    for (int m = tid; m < 4096; m += 256) {
      int r = m >> 7, col = m & 127;
      int kc = kc0 + r, k = kc >> 6, c = kc & 63;
      int g = col0 + col;
      Zs[m] = (g < TVN) ? Z[((k * CN + n) * CC + c) * TVN + g] : 0.f;
    }
    __syncthreads();
#pragma unroll 4
    for (int r = 0; r < 32; r++) {
      float4 wr = *(const float4*)&Ws[r * 64 + ty * 4];
      float4 xa = *(const float4*)&Zs[r * 128 + tx * 8];
      float4 xb = *(const float4*)&Zs[r * 128 + tx * 8 + 4];
      float w[4] = {wr.x, wr.y, wr.z, wr.w};
      float xv[8] = {xa.x, xa.y, xa.z, xa.w, xb.x, xb.y, xb.z, xb.w};
#pragma unroll
      for (int ri = 0; ri < 4; ri++)
#pragma unroll
        for (int j = 0; j < 8; j++) acc[ri][j] += w[ri] * xv[j];
    }
  }
  bool fast = (col0 + 128 <= TVN);
#pragma unroll
  for (int ri = 0; ri < 4; ri++) {
    int o = ty * 4 + ri;
    int base = (n * CC + o) * TVN + col0 + tx * 8;
    if (fast) {
      *(float4*)&y1[base] = make_float4(acc[ri][0], acc[ri][1], acc[ri][2], acc[ri][3]);
      *(float4*)&y1[base + 4] = make_float4(acc[ri][4], acc[ri][5], acc[ri][6], acc[ri][7]);
    } else {
#pragma unroll
      for (int j = 0; j < 8; j++)
        if (col0 + tx * 8 + j < TVN) y1[base + j] = acc[ri][j];
    }
  }
}

// ---------------------------------------------------------------------------
// K5: per-channel partial sums for BN (grid 64 x 16)
// ---------------------------------------------------------------------------
__global__ __launch_bounds__(256) void k_stats(const float4* __restrict__ in) {
  int o = blockIdx.x, s = blockIdx.y;
  int tid = threadIdx.x;
  float sum = 0.f, ss = 0.f;
  for (int m = tid; m < 7500; m += 256) {
    int nn = s * 4 + m / 1875;
    int j4 = m - (m / 1875) * 1875;
    float4 v = in[(nn * CC + o) * 1875 + j4];
    sum += v.x + v.y + v.z + v.w;
    ss += v.x * v.x + v.y * v.y + v.z * v.z + v.w * v.w;
  }
  __shared__ float s1[8], s2[8];
#pragma unroll
  for (int off = 16; off > 0; off >>= 1) {
    sum += __shfl_down_sync(0xffffffffu, sum, off);
    ss += __shfl_down_sync(0xffffffffu, ss, off);
  }
  if ((tid & 31) == 0) { s1[tid >> 5] = sum; s2[tid >> 5] = ss; }
  __syncthreads();
  if (tid == 0) {
    float a = 0.f, b = 0.f;
#pragma unroll
    for (int w = 0; w < 8; w++) { a += s1[w]; b += s2[w]; }
    g_partsum[o * 16 + s] = a;
    g_partss[o * 16 + s] = b;
  }
}

__global__ void k_bnfinal(const float* __restrict__ gamma, const float* __restrict__ beta) {
  int o = threadIdx.x;
  float a = 0.f, b = 0.f;
#pragma unroll
  for (int s = 0; s < 16; s++) { a += g_partsum[o * 16 + s]; b += g_partss[o * 16 + s]; }
  float inv = 1.0f / 480000.0f;
  float mu = a * inv;
  float var = b * inv - mu * mu;
  float A = gamma[o] * rsqrtf(var + EPSBN);
  g_bnA[o] = A;
  g_bnB[o] = beta[o] - mu * A;
}

// ---------------------------------------------------------------------------
// K6: out = relu(A[o]*in + B[o] + x)
// ---------------------------------------------------------------------------
__global__ __launch_bounds__(256) void k_addrelu(
    const float4* __restrict__ in, const float4* __restrict__ x,
    float4* __restrict__ out) {
  int i = blockIdx.x * 256 + threadIdx.x;
  int o = (i / 1875) & 63;
  float A = g_bnA[o], B = g_bnB[o];
  float4 v = in[i], xx = x[i], r;
  r.x = fmaxf(A * v.x + B + xx.x, 0.f);
  r.y = fmaxf(A * v.y + B + xx.y, 0.f);
  r.z = fmaxf(A * v.z + B + xx.z, 0.f);
  r.w = fmaxf(A * v.w + B + xx.w, 0.f);
  out[i] = r;
}

// ---------------------------------------------------------------------------
// K7: temporal conv KT=9 pad 4, 64x128 output tile, haloed smem (328 cols)
// ---------------------------------------------------------------------------
__global__ __launch_bounds__(256) void k_tcn(
    const float* __restrict__ y2, const float* __restrict__ wtT,
    float* __restrict__ yt) {
  __shared__ __align__(16) float y2cs[8 * 328];
  __shared__ __align__(16) float Ws[8 * 9 * 64];
  int n = blockIdx.y, col0 = blockIdx.x * 128;
  int tid = threadIdx.x;
  int ty = tid >> 4, tx = tid & 15;
  int o0 = ty * 4;
  float acc[4][8];
#pragma unroll
  for (int r = 0; r < 4; r++)
#pragma unroll
    for (int j = 0; j < 8; j++) acc[r][j] = 0.f;
  for (int cc = 0; cc < 8; cc++) {
    __syncthreads();
    for (int m = tid; m < 2624; m += 256) {
      int c = m / 328, lc = m - c * 328;
      int cg = cc * 8 + c;
      int gc = col0 - 100 + lc;
      y2cs[m] = (gc >= 0 && gc < TVN) ? y2[(n * CC + cg) * TVN + gc] : 0.f;
    }
    for (int m = tid; m < 4608; m += 256) Ws[m] = wtT[cc * 4608 + m];
    __syncthreads();
#pragma unroll
    for (int c = 0; c < 8; c++) {
      const float* xrow = &y2cs[c * 328 + tx * 8];
#pragma unroll
      for (int dt = 0; dt < 9; dt++) {
        float4 wr = *(const float4*)&Ws[(c * 9 + dt) * 64 + o0];
        float w[4] = {wr.x, wr.y, wr.z, wr.w};
        float xv[8];
#pragma unroll
        for (int q = 0; q < 8; q++) xv[q] = xrow[dt * 25 + q];
#pragma unroll
        for (int ri = 0; ri < 4; ri++)
#pragma unroll
          for (int j = 0; j < 8; j++) acc[ri][j] += w[ri] * xv[j];
      }
    }
  }
  bool fast = (col0 + 128 <= TVN);
#pragma unroll
  for (int ri = 0; ri < 4; ri++) {
    int base = (n * CC + o0 + ri) * TVN + col0 + tx * 8;
    if (fast) {
      *(float4*)&yt[base] = make_float4(acc[ri][0], acc[ri][1], acc[ri][2], acc[ri][3]);
      *(float4*)&yt[base + 4] = make_float4(acc[ri][4], acc[ri][5], acc[ri][6], acc[ri][7]);
    } else {
#pragma unroll
      for (int j = 0; j < 8; j++)
        if (col0 + tx * 8 + j < TVN) yt[base + j] = acc[ri][j];
    }
  }
}

__global__ void k_copyadj(const float* __restrict__ adj, float* __restrict__ out) {
  int i = blockIdx.x * 256 + threadIdx.x;
  if (i < 1875) out[30720000 + i] = adj[i];
}

extern "C" void kernel_launch(void* const* d_in, const int* in_sizes, int n_in,
                              void* d_out, int out_size) {
  const float* x   = (const float*)d_in[0];
  const float* adj = (const float*)d_in[1];
  const float* PA  = (const float*)d_in[2];
  const float* Wa  = (const float*)d_in[3];
  const float* ba  = (const float*)d_in[4];
  const float* Wb  = (const float*)d_in[5];
  const float* bb  = (const float*)d_in[6];
  const float* Wd  = (const float*)d_in[7];
  const float* g1  = (const float*)d_in[9];
  const float* b1  = (const float*)d_in[10];
  const float* Wt  = (const float*)d_in[11];
  const float* g2  = (const float*)d_in[13];
  const float* b2  = (const float*)d_in[14];
  float* out = (float*)d_out;

  float* sc = nullptr;
  cudaGetSymbolAddress((void**)&sc, g_scratch);

  k_prep<<<216, 256>>>(Wa, Wb, Wd, Wt, sc + OFF_W);

  dim3 gGemm(59, 64);  // 59 * 128 = 7552 >= 7500
  k_fafb<<<gGemm, 384>>>(x, sc + OFF_W, ba, bb, sc + OFF_FA, sc + OFF_FB);
  dim3 gS(3, 64);
  k_S<<<gS, 224>>>(adj, PA, sc + OFF_FA, sc + OFF_FB, sc + OFF_S);
  dim3 gZ(50, 64);
  k_Z<<<gZ, 256>>>(x, sc + OFF_S, sc + OFF_Z);
  k_yg<<<gGemm, 256>>>(sc + OFF_Z, sc + OFF_W + 6144, sc + OFF_YG);
  dim3 gSt(64, 16);
  k_stats<<<gSt, 256>>>((const float4*)(sc + OFF_YG));
  k_bnfinal<<<1, 64>>>(g1, b1);
  k_addrelu<<<30000, 256>>>((const float4*)(sc + OFF_YG), (const float4*)x,
                            (float4*)(sc + 0));
  k_tcn<<<gGemm, 256>>>(sc + 0, sc + OFF_W + 18432, sc + OFF_Z);
  k_stats<<<gSt, 256>>>((const float4*)(sc + OFF_Z));
  k_bnfinal<<<1, 64>>>(g2, b2);
  k_addrelu<<<30000, 256>>>((const float4*)(sc + OFF_Z), (const float4*)x,
                            (float4*)out);
  if (out_size > 30720000) k_copyadj<<<8, 256>>>(adj, out);
}

// round 6
// speedup vs baseline: 1.4348x; 1.4348x over previous
#include <cuda_runtime.h>
#include <math.h>

#define CN 64
#define CC 64
#define CT 300
#define CV 25
#define TVN 7500
#define ICN 16
#define EPSBN 1e-5f

static const int OFF_FA = 0;          // 23,040,000
static const int OFF_FB = 23040000;   // 23,040,000
static const int OFF_S  = 46080000;   // 120,000
static const int OFF_Z  = 46200000;   // 92,160,000  (later reused for yt)
static const int OFF_YG = 138360000;  // 30,720,000
static const int OFF_W  = 169080000;  // transposed weights
__device__ float g_scratch[169140000];
__device__ float g_partsum[1024];
__device__ float g_partss[1024];
__device__ float g_bnA[64];
__device__ float g_bnB[64];

// ---------------------------------------------------------------------------
// K0: weight transposes for coalesced tile loads
// ---------------------------------------------------------------------------
__global__ void k_prep(const float* __restrict__ Wa, const float* __restrict__ Wb,
                       const float* __restrict__ Wd, const float* __restrict__ Wt,
                       float* __restrict__ wout) {
  int idx = blockIdx.x * 256 + threadIdx.x;
  if (idx < 6144) {
    int c = idx / 96, row = idx - c * 96;
    wout[idx] = (row < 48) ? Wa[row * 64 + c] : Wb[(row - 48) * 64 + c];
  } else if (idx < 6144 + 12288) {
    int j = idx - 6144;
    int o = j & 63, kc = j >> 6;
    int k = kc >> 6, c = kc & 63;
    wout[idx] = Wd[k * 4096 + o * 64 + c];
  } else if (idx < 55296) {
    int j = idx - 18432;
    int o = j & 63, cdt = j >> 6;
    wout[idx] = Wt[o * 576 + cdt];
  }
}

// ---------------------------------------------------------------------------
// K1: fa/fb: GEMM 96rows x 64k x 128cols per block; cyclic-float4 columns
// ---------------------------------------------------------------------------
__global__ __launch_bounds__(384) void k_fafb(
    const float* __restrict__ x, const float* __restrict__ wabT,
    const float* __restrict__ ba, const float* __restrict__ bb,
    float* __restrict__ fa, float* __restrict__ fb) {
  __shared__ __align__(16) float WS[64 * 96];
  __shared__ __align__(16) float xs[64 * 128];
  int n = blockIdx.y, col0 = blockIdx.x * 128;
  int tid = threadIdx.x;
  for (int m = tid; m < 6144; m += 384) WS[m] = wabT[m];
  const float* xp = x + n * (CC * TVN);
  for (int m = tid; m < 8192; m += 384) {
    int c = m >> 7, col = m & 127;
    int g = col0 + col;
    xs[m] = (g < TVN) ? xp[c * TVN + g] : 0.f;
  }
  __syncthreads();
  int ty = tid >> 4, tx = tid & 15;  // 24 x 16
  float acc[4][8];
#pragma unroll
  for (int r = 0; r < 4; r++)
#pragma unroll
    for (int j = 0; j < 8; j++) acc[r][j] = 0.f;
#pragma unroll 4
  for (int k = 0; k < 64; k++) {
    float4 wr = *(const float4*)&WS[k * 96 + ty * 4];
    float4 xa = *(const float4*)&xs[k * 128 + tx * 4];
    float4 xb = *(const float4*)&xs[k * 128 + 64 + tx * 4];
    float w[4] = {wr.x, wr.y, wr.z, wr.w};
    float xv[8] = {xa.x, xa.y, xa.z, xa.w, xb.x, xb.y, xb.z, xb.w};
#pragma unroll
    for (int r = 0; r < 4; r++)
#pragma unroll
      for (int j = 0; j < 8; j++) acc[r][j] += w[r] * xv[j];
  }
  bool fast = (col0 + 128 <= TVN);
#pragma unroll
  for (int r = 0; r < 4; r++) {
    int row = ty * 4 + r;
    int rr = (row < 48) ? row : row - 48;
    float* outp = (row < 48) ? fa : fb;
    float bias = (row < 48) ? ba[rr] : bb[rr];
    int k = rr >> 4, i = rr & 15;
    int base = (k * CN + n) * (ICN * TVN) + i * TVN + col0;
    if (fast) {
      *(float4*)&outp[base + tx * 4] =
          make_float4(acc[r][0] + bias, acc[r][1] + bias, acc[r][2] + bias, acc[r][3] + bias);
      *(float4*)&outp[base + 64 + tx * 4] =
          make_float4(acc[r][4] + bias, acc[r][5] + bias, acc[r][6] + bias, acc[r][7] + bias);
    } else {
#pragma unroll
      for (int j = 0; j < 8; j++) {
        int col = (j < 4) ? tx * 4 + j : 64 + tx * 4 + (j - 4);
        if (col0 + col < TVN) outp[base + col] = acc[r][j] + bias;
      }
    }
  }
}

// ---------------------------------------------------------------------------
// K2: S = softmax_v((fa^T fb)/4800) + (adj+PA)
// ---------------------------------------------------------------------------
__global__ __launch_bounds__(224) void k_S(
    const float* __restrict__ adj, const float* __restrict__ PA,
    const float* __restrict__ fa, const float* __restrict__ fb,
    float* __restrict__ Sout) {
  int k = blockIdx.x, n = blockIdx.y;
  __shared__ float sfa[1600], sfb[1600];
  __shared__ float sP[8 * 625];
  __shared__ float sS[625];
  __shared__ float smx[25], sinv[25];
  const float* fap = fa + (k * CN + n) * (ICN * TVN);
  const float* fbp = fb + (k * CN + n) * (ICN * TVN);
  int tid = threadIdx.x;
  float acc[25];
#pragma unroll
  for (int q = 0; q < 25; q++) acc[q] = 0.f;
  int tile = tid % 25, es = tid / 25;
  int vt = (tile / 5) * 5, wt = (tile % 5) * 5;
  for (int ch = 0; ch < 75; ch++) {
    __syncthreads();
    int d0 = ch * 64;
    for (int m = tid; m < 1600; m += 224) {
      int e = m / 25, vv = m - e * 25;
      int d = d0 + e;
      int i = d / 300, t = d - i * 300;
      int addr = i * TVN + t * 25 + vv;
      sfa[m] = fap[addr];
      sfb[m] = fbp[addr];
    }
    __syncthreads();
    if (tid < 200) {
#pragma unroll
      for (int ee = 0; ee < 8; ee++) {
        int e = es * 8 + ee;
        float av[5], bv[5];
#pragma unroll
        for (int q = 0; q < 5; q++) { av[q] = sfa[e * 25 + vt + q]; bv[q] = sfb[e * 25 + wt + q]; }
#pragma unroll
        for (int a2 = 0; a2 < 5; a2++)
#pragma unroll
          for (int b2 = 0; b2 < 5; b2++) acc[a2 * 5 + b2] += av[a2] * bv[b2];
      }
    }
  }
  __syncthreads();
  if (tid < 200) {
#pragma unroll
    for (int a2 = 0; a2 < 5; a2++)
#pragma unroll
      for (int b2 = 0; b2 < 5; b2++)
        sP[es * 625 + (vt + a2) * 25 + (wt + b2)] = acc[a2 * 5 + b2];
  }
  __syncthreads();
  for (int m = tid; m < 625; m += 224) {
    float s = 0.f;
#pragma unroll
    for (int e = 0; e < 8; e++) s += sP[e * 625 + m];
    sS[m] = s * (1.0f / 4800.0f);
  }
  __syncthreads();
  if (tid < 25) {
    float mx = -1e30f;
    for (int v = 0; v < 25; v++) mx = fmaxf(mx, sS[v * 25 + tid]);
    float sm = 0.f;
    for (int v = 0; v < 25; v++) sm += expf(sS[v * 25 + tid] - mx);
    smx[tid] = mx;
    sinv[tid] = 1.f / sm;
  }
  __syncthreads();
  float* so = Sout + (k * CN + n) * 625;
  for (int m = tid; m < 625; m += 224) {
    int w = m % 25;
    so[m] = expf(sS[m] - smx[w]) * sinv[w] + adj[k * 625 + m] + PA[k * 625 + m];
  }
}

// ---------------------------------------------------------------------------
// K3: Z[k,n,c,t,w] = sum_v x[n,c,t,v] * S[k,n,v,w]
// ---------------------------------------------------------------------------
__global__ __launch_bounds__(256) void k_Z(
    const float* __restrict__ x, const float* __restrict__ Sbuf,
    float* __restrict__ Z) {
  int n = blockIdx.y, t0 = blockIdx.x * 6;
  __shared__ float Ss[1875];
  __shared__ float xs[64 * 150];
  int tid = threadIdx.x;
  for (int m = tid; m < 1875; m += 256) {
    int k = m / 625;
    Ss[m] = Sbuf[(k * CN + n) * 625 + (m - k * 625)];
  }
  const float* xp = x + n * (CC * TVN) + t0 * 25;
  for (int m = tid; m < 64 * 150; m += 256) {
    int c = m / 150, col = m - c * 150;
    xs[m] = xp[c * TVN + col];
  }
  __syncthreads();
  for (int tsk = tid; tsk < 720; tsk += 256) {
    int k = tsk / 240, r = tsk - k * 240;
    int cg = r / 30;
    int r2 = r - cg * 30;
    int tt = r2 / 5, wt = r2 - tt * 5;
    int cb = cg * 8, w0 = wt * 5;
    const float* sp = Ss + k * 625;
    float acc[8][5];
#pragma unroll
    for (int a2 = 0; a2 < 8; a2++)
#pragma unroll
      for (int b2 = 0; b2 < 5; b2++) acc[a2][b2] = 0.f;
    for (int v = 0; v < 25; v++) {
      float xv[8], sv[5];
#pragma unroll
      for (int ci = 0; ci < 8; ci++) xv[ci] = xs[(cb + ci) * 150 + tt * 25 + v];
#pragma unroll
      for (int wi = 0; wi < 5; wi++) sv[wi] = sp[v * 25 + w0 + wi];
#pragma unroll
      for (int ci = 0; ci < 8; ci++)
#pragma unroll
        for (int wi = 0; wi < 5; wi++) acc[ci][wi] += xv[ci] * sv[wi];
    }
#pragma unroll
    for (int ci = 0; ci < 8; ci++) {
      int base = ((k * CN + n) * CC + cb + ci) * TVN + (t0 + tt) * 25 + w0;
#pragma unroll
      for (int wi = 0; wi < 5; wi++) Z[base + wi] = acc[ci][wi];
    }
  }
}

// ---------------------------------------------------------------------------
// K4: y1 = WdT(192x64)^T @ Z(192 x cols); 64x128 tile, cyclic-float4 columns
// ---------------------------------------------------------------------------
__global__ __launch_bounds__(256) void k_yg(
    const float* __restrict__ Z, const float* __restrict__ wdT,
    float* __restrict__ y1) {
  __shared__ __align__(16) float Ws[32 * 64];
  __shared__ __align__(16) float Zs[32 * 128];
  int n = blockIdx.y, col0 = blockIdx.x * 128;
  int tid = threadIdx.x;
  int ty = tid >> 4, tx = tid & 15;  // 16 x 16
  float acc[4][8];
#pragma unroll
  for (int r = 0; r < 4; r++)
#pragma unroll
    for (int j = 0; j < 8; j++) acc[r][j] = 0.f;
  for (int ch = 0; ch < 6; ch++) {
    __syncthreads();
    int kc0 = ch * 32;
    for (int m = tid; m < 2048; m += 256) Ws[m] = wdT[kc0 * 64 + m];
    for (int m = tid; m < 4096; m += 256) {
      int r = m >> 7, col = m & 127;
      int kc = kc0 + r, k = kc >> 6, c = kc & 63;
      int g = col0 + col;
      Zs[m] = (g < TVN) ? Z[((k * CN + n) * CC + c) * TVN + g] : 0.f;
    }
    __syncthreads();
#pragma unroll 4
    for (int r = 0; r < 32; r++) {
      float4 wr = *(const float4*)&Ws[r * 64 + ty * 4];
      float4 xa = *(const float4*)&Zs[r * 128 + tx * 4];
      float4 xb = *(const float4*)&Zs[r * 128 + 64 + tx * 4];
      float w[4] = {wr.x, wr.y, wr.z, wr.w};
      float xv[8] = {xa.x, xa.y, xa.z, xa.w, xb.x, xb.y, xb.z, xb.w};
#pragma unroll
      for (int ri = 0; ri < 4; ri++)
#pragma unroll
        for (int j = 0; j < 8; j++) acc[ri][j] += w[ri] * xv[j];
    }
  }
  bool fast = (col0 + 128 <= TVN);
#pragma unroll
  for (int ri = 0; ri < 4; ri++) {
    int o = ty * 4 + ri;
    int base = (n * CC + o) * TVN + col0;
    if (fast) {
      *(float4*)&y1[base + tx * 4] = make_float4(acc[ri][0], acc[ri][1], acc[ri][2], acc[ri][3]);
      *(float4*)&y1[base + 64 + tx * 4] = make_float4(acc[ri][4], acc[ri][5], acc[ri][6], acc[ri][7]);
    } else {
#pragma unroll
      for (int j = 0; j < 8; j++) {
        int col = (j < 4) ? tx * 4 + j : 64 + tx * 4 + (j - 4);
        if (col0 + col < TVN) y1[base + col] = acc[ri][j];
      }
    }
  }
}

// ---------------------------------------------------------------------------
// K5: per-channel partial sums for BN (grid 64 x 16)
// ---------------------------------------------------------------------------
__global__ __launch_bounds__(256) void k_stats(const float4* __restrict__ in) {
  int o = blockIdx.x, s = blockIdx.y;
  int tid = threadIdx.x;
  float sum = 0.f, ss = 0.f;
  for (int m = tid; m < 7500; m += 256) {
    int nn = s * 4 + m / 1875;
    int j4 = m - (m / 1875) * 1875;
    float4 v = in[(nn * CC + o) * 1875 + j4];
    sum += v.x + v.y + v.z + v.w;
    ss += v.x * v.x + v.y * v.y + v.z * v.z + v.w * v.w;
  }
  __shared__ float s1[8], s2[8];
#pragma unroll
  for (int off = 16; off > 0; off >>= 1) {
    sum += __shfl_down_sync(0xffffffffu, sum, off);
    ss += __shfl_down_sync(0xffffffffu, ss, off);
  }
  if ((tid & 31) == 0) { s1[tid >> 5] = sum; s2[tid >> 5] = ss; }
  __syncthreads();
  if (tid == 0) {
    float a = 0.f, b = 0.f;
#pragma unroll
    for (int w = 0; w < 8; w++) { a += s1[w]; b += s2[w]; }
    g_partsum[o * 16 + s] = a;
    g_partss[o * 16 + s] = b;
  }
}

__global__ void k_bnfinal(const float* __restrict__ gamma, const float* __restrict__ beta) {
  int o = threadIdx.x;
  float a = 0.f, b = 0.f;
#pragma unroll
  for (int s = 0; s < 16; s++) { a += g_partsum[o * 16 + s]; b += g_partss[o * 16 + s]; }
  float inv = 1.0f / 480000.0f;
  float mu = a * inv;
  float var = b * inv - mu * mu;
  float A = gamma[o] * rsqrtf(var + EPSBN);
  g_bnA[o] = A;
  g_bnB[o] = beta[o] - mu * A;
}

// ---------------------------------------------------------------------------
// K6: out = relu(A[o]*in + B[o] + x)  (final epilogue only)
// ---------------------------------------------------------------------------
__global__ __launch_bounds__(256) void k_addrelu(
    const float4* __restrict__ in, const float4* __restrict__ x,
    float4* __restrict__ out) {
  int i = blockIdx.x * 256 + threadIdx.x;
  int o = (i / 1875) & 63;
  float A = g_bnA[o], B = g_bnB[o];
  float4 v = in[i], xx = x[i], r;
  r.x = fmaxf(A * v.x + B + xx.x, 0.f);
  r.y = fmaxf(A * v.y + B + xx.y, 0.f);
  r.z = fmaxf(A * v.z + B + xx.z, 0.f);
  r.w = fmaxf(A * v.w + B + xx.w, 0.f);
  out[i] = r;
}

// ---------------------------------------------------------------------------
// K7: temporal conv with fused BN1+residual+ReLU on load.
// y2(c,gc) = relu(A[c]*y1 + B[c] + x) computed in the smem-fill stage.
// 64x128 output tile, cyclic scalar columns (conflict-free).
// ---------------------------------------------------------------------------
__global__ __launch_bounds__(256) void k_tcn(
    const float* __restrict__ y1, const float* __restrict__ x,
    const float* __restrict__ wtT, float* __restrict__ yt) {
  __shared__ __align__(16) float y2cs[8 * 328];
  __shared__ __align__(16) float Ws[8 * 9 * 64];
  __shared__ float sA[64], sB[64];
  int n = blockIdx.y, col0 = blockIdx.x * 128;
  int tid = threadIdx.x;
  if (tid < 64) { sA[tid] = g_bnA[tid]; sB[tid] = g_bnB[tid]; }
  int ty = tid >> 4, tx = tid & 15;
  int o0 = ty * 4;
  float acc[4][8];
#pragma unroll
  for (int r = 0; r < 4; r++)
#pragma unroll
    for (int j = 0; j < 8; j++) acc[r][j] = 0.f;
  for (int cc = 0; cc < 8; cc++) {
    __syncthreads();
    for (int m = tid; m < 2624; m += 256) {
      int c = m / 328, lc = m - c * 328;
      int cg = cc * 8 + c;
      int gc = col0 - 100 + lc;
      float v = 0.f;
      if (gc >= 0 && gc < TVN) {
        int gidx = (n * CC + cg) * TVN + gc;
        v = fmaxf(sA[cg] * y1[gidx] + sB[cg] + x[gidx], 0.f);
      }
      y2cs[m] = v;
    }
    for (int m = tid; m < 4608; m += 256) Ws[m] = wtT[cc * 4608 + m];
    __syncthreads();
#pragma unroll
    for (int c = 0; c < 8; c++) {
      const float* xrow = &y2cs[c * 328 + tx];
#pragma unroll
      for (int dt = 0; dt < 9; dt++) {
        float4 wr = *(const float4*)&Ws[(c * 9 + dt) * 64 + o0];
        float w[4] = {wr.x, wr.y, wr.z, wr.w};
        float xv[8];
#pragma unroll
        for (int q = 0; q < 8; q++) xv[q] = xrow[dt * 25 + 16 * q];
#pragma unroll
        for (int ri = 0; ri < 4; ri++)
#pragma unroll
          for (int j = 0; j < 8; j++) acc[ri][j] += w[ri] * xv[j];
      }
    }
  }
  bool fast = (col0 + 128 <= TVN);
#pragma unroll
  for (int ri = 0; ri < 4; ri++) {
    int base = (n * CC + o0 + ri) * TVN + col0 + tx;
    if (fast) {
#pragma unroll
      for (int j = 0; j < 8; j++) yt[base + 16 * j] = acc[ri][j];
    } else {
#pragma unroll
      for (int j = 0; j < 8; j++)
        if (col0 + tx + 16 * j < TVN) yt[base + 16 * j] = acc[ri][j];
    }
  }
}

__global__ void k_copyadj(const float* __restrict__ adj, float* __restrict__ out) {
  int i = blockIdx.x * 256 + threadIdx.x;
  if (i < 1875) out[30720000 + i] = adj[i];
}

extern "C" void kernel_launch(void* const* d_in, const int* in_sizes, int n_in,
                              void* d_out, int out_size) {
  const float* x   = (const float*)d_in[0];
  const float* adj = (const float*)d_in[1];
  const float* PA  = (const float*)d_in[2];
  const float* Wa  = (const float*)d_in[3];
  const float* ba  = (const float*)d_in[4];
  const float* Wb  = (const float*)d_in[5];
  const float* bb  = (const float*)d_in[6];
  const float* Wd  = (const float*)d_in[7];
  const float* g1  = (const float*)d_in[9];
  const float* b1  = (const float*)d_in[10];
  const float* Wt  = (const float*)d_in[11];
  const float* g2  = (const float*)d_in[13];
  const float* b2  = (const float*)d_in[14];
  float* out = (float*)d_out;

  float* sc = nullptr;
  cudaGetSymbolAddress((void**)&sc, g_scratch);

  k_prep<<<216, 256>>>(Wa, Wb, Wd, Wt, sc + OFF_W);

  dim3 gGemm(59, 64);  // 59 * 128 = 7552 >= 7500
  k_fafb<<<gGemm, 384>>>(x, sc + OFF_W, ba, bb, sc + OFF_FA, sc + OFF_FB);
  dim3 gS(3, 64);
  k_S<<<gS, 224>>>(adj, PA, sc + OFF_FA, sc + OFF_FB, sc + OFF_S);
  dim3 gZ(50, 64);
  k_Z<<<gZ, 256>>>(x, sc + OFF_S, sc + OFF_Z);
  k_yg<<<gGemm, 256>>>(sc + OFF_Z, sc + OFF_W + 6144, sc + OFF_YG);
  dim3 gSt(64, 16);
  k_stats<<<gSt, 256>>>((const float4*)(sc + OFF_YG));
  k_bnfinal<<<1, 64>>>(g1, b1);
  // tcn consumes y1 + x with fused BN1+residual+ReLU; writes yt into Z region
  k_tcn<<<gGemm, 256>>>(sc + OFF_YG, x, sc + OFF_W + 18432, sc + OFF_Z);
  k_stats<<<gSt, 256>>>((const float4*)(sc + OFF_Z));
  k_bnfinal<<<1, 64>>>(g2, b2);
  k_addrelu<<<30000, 256>>>((const float4*)(sc + OFF_Z), (const float4*)x,
                            (float4*)out);
  if (out_size > 30720000) k_copyadj<<<8, 256>>>(adj, out);
}

// round 7
// speedup vs baseline: 2.1839x; 1.5221x over previous
#include <cuda_runtime.h>
#include <math.h>

#define CN 64
#define CC 64
#define CT 300
#define CV 25
#define TVN 7500
#define ICN 16
#define EPSBN 1e-5f

static const int OFF_FA = 0;          // 23,040,000
static const int OFF_FB = 23040000;   // 23,040,000
static const int OFF_S  = 46080000;   // 120,000
static const int OFF_Z  = 46200000;   // yt lives here (30,720,000 used)
static const int OFF_YG = 138360000;  // 30,720,000
static const int OFF_W  = 169080000;  // transposed weights
__device__ float g_scratch[169140000];
__device__ float g_partsum[1024];
__device__ float g_partss[1024];
__device__ float g_bnA[64];
__device__ float g_bnB[64];

// ---------------------------------------------------------------------------
// K0: weight transposes for coalesced tile loads
// ---------------------------------------------------------------------------
__global__ void k_prep(const float* __restrict__ Wa, const float* __restrict__ Wb,
                       const float* __restrict__ Wd, const float* __restrict__ Wt,
                       float* __restrict__ wout) {
  int idx = blockIdx.x * 256 + threadIdx.x;
  if (idx < 6144) {
    int c = idx / 96, row = idx - c * 96;
    wout[idx] = (row < 48) ? Wa[row * 64 + c] : Wb[(row - 48) * 64 + c];
  } else if (idx < 6144 + 12288) {
    int j = idx - 6144;
    int o = j & 63, kc = j >> 6;
    int k = kc >> 6, c = kc & 63;
    wout[idx] = Wd[k * 4096 + o * 64 + c];
  } else if (idx < 55296) {
    int j = idx - 18432;
    int o = j & 63, cdt = j >> 6;
    wout[idx] = Wt[o * 576 + cdt];
  }
}

// ---------------------------------------------------------------------------
// K1: fa/fb: GEMM 96rows x 64k x 128cols per block; cyclic-float4 columns
// ---------------------------------------------------------------------------
__global__ __launch_bounds__(384) void k_fafb(
    const float* __restrict__ x, const float* __restrict__ wabT,
    const float* __restrict__ ba, const float* __restrict__ bb,
    float* __restrict__ fa, float* __restrict__ fb) {
  __shared__ __align__(16) float WS[64 * 96];
  __shared__ __align__(16) float xs[64 * 128];
  int n = blockIdx.y, col0 = blockIdx.x * 128;
  int tid = threadIdx.x;
  for (int m = tid; m < 6144; m += 384) WS[m] = wabT[m];
  const float* xp = x + n * (CC * TVN);
  for (int m = tid; m < 8192; m += 384) {
    int c = m >> 7, col = m & 127;
    int g = col0 + col;
    xs[m] = (g < TVN) ? xp[c * TVN + g] : 0.f;
  }
  __syncthreads();
  int ty = tid >> 4, tx = tid & 15;  // 24 x 16
  float acc[4][8];
#pragma unroll
  for (int r = 0; r < 4; r++)
#pragma unroll
    for (int j = 0; j < 8; j++) acc[r][j] = 0.f;
#pragma unroll 4
  for (int k = 0; k < 64; k++) {
    float4 wr = *(const float4*)&WS[k * 96 + ty * 4];
    float4 xa = *(const float4*)&xs[k * 128 + tx * 4];
    float4 xb = *(const float4*)&xs[k * 128 + 64 + tx * 4];
    float w[4] = {wr.x, wr.y, wr.z, wr.w};
    float xv[8] = {xa.x, xa.y, xa.z, xa.w, xb.x, xb.y, xb.z, xb.w};
#pragma unroll
    for (int r = 0; r < 4; r++)
#pragma unroll
      for (int j = 0; j < 8; j++) acc[r][j] += w[r] * xv[j];
  }
  bool fast = (col0 + 128 <= TVN);
#pragma unroll
  for (int r = 0; r < 4; r++) {
    int row = ty * 4 + r;
    int rr = (row < 48) ? row : row - 48;
    float* outp = (row < 48) ? fa : fb;
    float bias = (row < 48) ? ba[rr] : bb[rr];
    int k = rr >> 4, i = rr & 15;
    int base = (k * CN + n) * (ICN * TVN) + i * TVN + col0;
    if (fast) {
      *(float4*)&outp[base + tx * 4] =
          make_float4(acc[r][0] + bias, acc[r][1] + bias, acc[r][2] + bias, acc[r][3] + bias);
      *(float4*)&outp[base + 64 + tx * 4] =
          make_float4(acc[r][4] + bias, acc[r][5] + bias, acc[r][6] + bias, acc[r][7] + bias);
    } else {
#pragma unroll
      for (int j = 0; j < 8; j++) {
        int col = (j < 4) ? tx * 4 + j : 64 + tx * 4 + (j - 4);
        if (col0 + col < TVN) outp[base + col] = acc[r][j] + bias;
      }
    }
  }
}

// ---------------------------------------------------------------------------
// K2: S = softmax_v((fa^T fb)/4800) + (adj+PA)
// ---------------------------------------------------------------------------
__global__ __launch_bounds__(224) void k_S(
    const float* __restrict__ adj, const float* __restrict__ PA,
    const float* __restrict__ fa, const float* __restrict__ fb,
    float* __restrict__ Sout) {
  int k = blockIdx.x, n = blockIdx.y;
  __shared__ float sfa[1600], sfb[1600];
  __shared__ float sP[8 * 625];
  __shared__ float sS[625];
  __shared__ float smx[25], sinv[25];
  const float* fap = fa + (k * CN + n) * (ICN * TVN);
  const float* fbp = fb + (k * CN + n) * (ICN * TVN);
  int tid = threadIdx.x;
  float acc[25];
#pragma unroll
  for (int q = 0; q < 25; q++) acc[q] = 0.f;
  int tile = tid % 25, es = tid / 25;
  int vt = (tile / 5) * 5, wt = (tile % 5) * 5;
  for (int ch = 0; ch < 75; ch++) {
    __syncthreads();
    int d0 = ch * 64;
    for (int m = tid; m < 1600; m += 224) {
      int e = m / 25, vv = m - e * 25;
      int d = d0 + e;
      int i = d / 300, t = d - i * 300;
      int addr = i * TVN + t * 25 + vv;
      sfa[m] = fap[addr];
      sfb[m] = fbp[addr];
    }
    __syncthreads();
    if (tid < 200) {
#pragma unroll
      for (int ee = 0; ee < 8; ee++) {
        int e = es * 8 + ee;
        float av[5], bv[5];
#pragma unroll
        for (int q = 0; q < 5; q++) { av[q] = sfa[e * 25 + vt + q]; bv[q] = sfb[e * 25 + wt + q]; }
#pragma unroll
        for (int a2 = 0; a2 < 5; a2++)
#pragma unroll
          for (int b2 = 0; b2 < 5; b2++) acc[a2 * 5 + b2] += av[a2] * bv[b2];
      }
    }
  }
  __syncthreads();
  if (tid < 200) {
#pragma unroll
    for (int a2 = 0; a2 < 5; a2++)
#pragma unroll
      for (int b2 = 0; b2 < 5; b2++)
        sP[es * 625 + (vt + a2) * 25 + (wt + b2)] = acc[a2 * 5 + b2];
  }
  __syncthreads();
  for (int m = tid; m < 625; m += 224) {
    float s = 0.f;
#pragma unroll
    for (int e = 0; e < 8; e++) s += sP[e * 625 + m];
    sS[m] = s * (1.0f / 4800.0f);
  }
  __syncthreads();
  if (tid < 25) {
    float mx = -1e30f;
    for (int v = 0; v < 25; v++) mx = fmaxf(mx, sS[v * 25 + tid]);
    float sm = 0.f;
    for (int v = 0; v < 25; v++) sm += expf(sS[v * 25 + tid] - mx);
    smx[tid] = mx;
    sinv[tid] = 1.f / sm;
  }
  __syncthreads();
  float* so = Sout + (k * CN + n) * 625;
  for (int m = tid; m < 625; m += 224) {
    int w = m % 25;
    so[m] = expf(sS[m] - smx[w]) * sinv[w] + adj[k * 625 + m] + PA[k * 625 + m];
  }
}

// ---------------------------------------------------------------------------
// K3: fused Z + Wd-GEMM. Per block (n, 6-t tile = 150 cols):
//   for k in 0..2: Phase A builds Zk[64c x 150] in smem from x-tile and S_k;
//                  Phase B accumulates y1 += WdT_k^T @ Zk (64-deep).
// Z never touches global memory.
// smem floats: WdTs 4096 | Ss 1875 | xs 9600 | Zk 10240 (cols padded to 160)
// ---------------------------------------------------------------------------
#define ZS_WD 0
#define ZS_SS 4096
#define ZS_XS 5972
#define ZS_ZK 15572
#define ZS_TOT 25812

__global__ __launch_bounds__(256, 2) void k_zyg(
    const float* __restrict__ x, const float* __restrict__ Sbuf,
    const float* __restrict__ wdT, float* __restrict__ y1) {
  extern __shared__ __align__(16) float sm[];
  float* WdTs = sm + ZS_WD;
  float* Ss   = sm + ZS_SS;
  float* xs   = sm + ZS_XS;
  float* Zk   = sm + ZS_ZK;
  int n = blockIdx.y, t0 = blockIdx.x * 6;
  int col0 = t0 * 25;  // 150-aligned
  int tid = threadIdx.x;
  for (int m = tid; m < 1875; m += 256) {
    int k = m / 625;
    Ss[m] = Sbuf[(k * CN + n) * 625 + (m - k * 625)];
  }
  const float* xp = x + n * (CC * TVN) + col0;
  for (int m = tid; m < 9600; m += 256) {
    int c = m / 150, col = m - c * 150;
    xs[m] = xp[c * TVN + col];
  }
  for (int m = tid; m < 10240; m += 256) Zk[m] = 0.f;

  int ty = tid >> 4, tx = tid & 15;  // 16 x 16 for Phase B
  float acc[4][10];
#pragma unroll
  for (int r = 0; r < 4; r++)
#pragma unroll
    for (int j = 0; j < 10; j++) acc[r][j] = 0.f;

  // Phase A task decode (stable across k)
  int cgA = 0, ttA = 0, wtA = 0;
  bool doA = (tid < 240);
  if (doA) {
    int r = tid;
    cgA = r / 30;
    int r2 = r - cgA * 30;
    ttA = r2 / 5;
    wtA = r2 - ttA * 5;
  }
  int cbA = cgA * 8, w0A = wtA * 5;

  for (int k = 0; k < 3; k++) {
    __syncthreads();  // initial loads done (k=0); Phase B(k-1) done (k>0)
    for (int m = tid; m < 4096; m += 256) WdTs[m] = wdT[k * 4096 + m];
    if (doA) {
      const float* sp = Ss + k * 625;
      float a2[8][5];
#pragma unroll
      for (int ci = 0; ci < 8; ci++)
#pragma unroll
        for (int wi = 0; wi < 5; wi++) a2[ci][wi] = 0.f;
      for (int v = 0; v < 25; v++) {
        float xv[8], sv[5];
#pragma unroll
        for (int ci = 0; ci < 8; ci++) xv[ci] = xs[(cbA + ci) * 150 + ttA * 25 + v];
#pragma unroll
        for (int wi = 0; wi < 5; wi++) sv[wi] = sp[v * 25 + w0A + wi];
#pragma unroll
        for (int ci = 0; ci < 8; ci++)
#pragma unroll
          for (int wi = 0; wi < 5; wi++) a2[ci][wi] += xv[ci] * sv[wi];
      }
#pragma unroll
      for (int ci = 0; ci < 8; ci++)
#pragma unroll
        for (int wi = 0; wi < 5; wi++)
          Zk[(cbA + ci) * 160 + ttA * 25 + w0A + wi] = a2[ci][wi];
    }
    __syncthreads();
#pragma unroll 2
    for (int c = 0; c < 64; c++) {
      float4 wr = *(const float4*)&WdTs[c * 64 + ty * 4];
      float w[4] = {wr.x, wr.y, wr.z, wr.w};
      float xv[10];
#pragma unroll
      for (int j = 0; j < 10; j++) xv[j] = Zk[c * 160 + tx + 16 * j];
#pragma unroll
      for (int r = 0; r < 4; r++)
#pragma unroll
        for (int j = 0; j < 10; j++) acc[r][j] += w[r] * xv[j];
    }
  }
#pragma unroll
  for (int r = 0; r < 4; r++) {
    int o = ty * 4 + r;
    int base = (n * CC + o) * TVN + col0;
#pragma unroll
    for (int j = 0; j < 10; j++) {
      int cl = tx + 16 * j;
      if (cl < 150) y1[base + cl] = acc[r][j];
    }
  }
}

// ---------------------------------------------------------------------------
// K5: per-channel partial sums for BN (grid 64 x 16)
// ---------------------------------------------------------------------------
__global__ __launch_bounds__(256) void k_stats(const float4* __restrict__ in) {
  int o = blockIdx.x, s = blockIdx.y;
  int tid = threadIdx.x;
  float sum = 0.f, ss = 0.f;
  for (int m = tid; m < 7500; m += 256) {
    int nn = s * 4 + m / 1875;
    int j4 = m - (m / 1875) * 1875;
    float4 v = in[(nn * CC + o) * 1875 + j4];
    sum += v.x + v.y + v.z + v.w;
    ss += v.x * v.x + v.y * v.y + v.z * v.z + v.w * v.w;
  }
  __shared__ float s1[8], s2[8];
#pragma unroll
  for (int off = 16; off > 0; off >>= 1) {
    sum += __shfl_down_sync(0xffffffffu, sum, off);
    ss += __shfl_down_sync(0xffffffffu, ss, off);
  }
  if ((tid & 31) == 0) { s1[tid >> 5] = sum; s2[tid >> 5] = ss; }
  __syncthreads();
  if (tid == 0) {
    float a = 0.f, b = 0.f;
#pragma unroll
    for (int w = 0; w < 8; w++) { a += s1[w]; b += s2[w]; }
    g_partsum[o * 16 + s] = a;
    g_partss[o * 16 + s] = b;
  }
}

__global__ void k_bnfinal(const float* __restrict__ gamma, const float* __restrict__ beta) {
  int o = threadIdx.x;
  float a = 0.f, b = 0.f;
#pragma unroll
  for (int s = 0; s < 16; s++) { a += g_partsum[o * 16 + s]; b += g_partss[o * 16 + s]; }
  float inv = 1.0f / 480000.0f;
  float mu = a * inv;
  float var = b * inv - mu * mu;
  float A = gamma[o] * rsqrtf(var + EPSBN);
  g_bnA[o] = A;
  g_bnB[o] = beta[o] - mu * A;
}

// ---------------------------------------------------------------------------
// K6: out = relu(A[o]*in + B[o] + x)  (final epilogue only)
// ---------------------------------------------------------------------------
__global__ __launch_bounds__(256) void k_addrelu(
    const float4* __restrict__ in, const float4* __restrict__ x,
    float4* __restrict__ out) {
  int i = blockIdx.x * 256 + threadIdx.x;
  int o = (i / 1875) & 63;
  float A = g_bnA[o], B = g_bnB[o];
  float4 v = in[i], xx = x[i], r;
  r.x = fmaxf(A * v.x + B + xx.x, 0.f);
  r.y = fmaxf(A * v.y + B + xx.y, 0.f);
  r.z = fmaxf(A * v.z + B + xx.z, 0.f);
  r.w = fmaxf(A * v.w + B + xx.w, 0.f);
  out[i] = r;
}

// ---------------------------------------------------------------------------
// K7: temporal conv, fused BN1+residual+ReLU on load.
// 64 x 256 output tile, 512 threads, 4o x 8col cyclic (stride 32).
// ---------------------------------------------------------------------------
__global__ __launch_bounds__(512) void k_tcn(
    const float* __restrict__ y1, const float* __restrict__ x,
    const float* __restrict__ wtT, float* __restrict__ yt) {
  __shared__ __align__(16) float y2cs[8 * 456];
  __shared__ __align__(16) float Ws[4608];
  __shared__ float sA[64], sB[64];
  int n = blockIdx.y, col0 = blockIdx.x * 256;
  int tid = threadIdx.x;
  if (tid < 64) { sA[tid] = g_bnA[tid]; sB[tid] = g_bnB[tid]; }
  int ty = tid >> 5, tx = tid & 31;
  int o0 = ty * 4;
  float acc[4][8];
#pragma unroll
  for (int r = 0; r < 4; r++)
#pragma unroll
    for (int j = 0; j < 8; j++) acc[r][j] = 0.f;
  for (int cc = 0; cc < 8; cc++) {
    __syncthreads();
    for (int m = tid; m < 3648; m += 512) {
      int c = m / 456, lc = m - c * 456;
      int cg = cc * 8 + c;
      int gc = col0 - 100 + lc;
      float v = 0.f;
      if (gc >= 0 && gc < TVN) {
        int gidx = (n * CC + cg) * TVN + gc;
        v = fmaxf(sA[cg] * y1[gidx] + sB[cg] + x[gidx], 0.f);
      }
      y2cs[m] = v;
    }
    for (int m = tid; m < 4608; m += 512) Ws[m] = wtT[cc * 4608 + m];
    __syncthreads();
#pragma unroll
    for (int c = 0; c < 8; c++) {
      const float* xrow = &y2cs[c * 456 + tx];
#pragma unroll
      for (int dt = 0; dt < 9; dt++) {
        float4 wr = *(const float4*)&Ws[(c * 9 + dt) * 64 + o0];
        float w[4] = {wr.x, wr.y, wr.z, wr.w};
        float xv[8];
#pragma unroll
        for (int q = 0; q < 8; q++) xv[q] = xrow[dt * 25 + 32 * q];
#pragma unroll
        for (int ri = 0; ri < 4; ri++)
#pragma unroll
          for (int j = 0; j < 8; j++) acc[ri][j] += w[ri] * xv[j];
      }
    }
  }
  bool fast = (col0 + 256 <= TVN);
#pragma unroll
  for (int ri = 0; ri < 4; ri++) {
    int base = (n * CC + o0 + ri) * TVN + col0 + tx;
    if (fast) {
#pragma unroll
      for (int j = 0; j < 8; j++) yt[base + 32 * j] = acc[ri][j];
    } else {
#pragma unroll
      for (int j = 0; j < 8; j++)
        if (col0 + tx + 32 * j < TVN) yt[base + 32 * j] = acc[ri][j];
    }
  }
}

__global__ void k_copyadj(const float* __restrict__ adj, float* __restrict__ out) {
  int i = blockIdx.x * 256 + threadIdx.x;
  if (i < 1875) out[30720000 + i] = adj[i];
}

extern "C" void kernel_launch(void* const* d_in, const int* in_sizes, int n_in,
                              void* d_out, int out_size) {
  const float* x   = (const float*)d_in[0];
  const float* adj = (const float*)d_in[1];
  const float* PA  = (const float*)d_in[2];
  const float* Wa  = (const float*)d_in[3];
  const float* ba  = (const float*)d_in[4];
  const float* Wb  = (const float*)d_in[5];
  const float* bb  = (const float*)d_in[6];
  const float* Wd  = (const float*)d_in[7];
  const float* g1  = (const float*)d_in[9];
  const float* b1  = (const float*)d_in[10];
  const float* Wt  = (const float*)d_in[11];
  const float* g2  = (const float*)d_in[13];
  const float* b2  = (const float*)d_in[14];
  float* out = (float*)d_out;

  float* sc = nullptr;
  cudaGetSymbolAddress((void**)&sc, g_scratch);

  static int smem_set = 0;
  if (!smem_set) {
    cudaFuncSetAttribute(k_zyg, cudaFuncAttributeMaxDynamicSharedMemorySize,
                         ZS_TOT * 4);
    smem_set = 1;
  }

  k_prep<<<216, 256>>>(Wa, Wb, Wd, Wt, sc + OFF_W);

  dim3 gGemm(59, 64);
  k_fafb<<<gGemm, 384>>>(x, sc + OFF_W, ba, bb, sc + OFF_FA, sc + OFF_FB);
  dim3 gS(3, 64);
  k_S<<<gS, 224>>>(adj, PA, sc + OFF_FA, sc + OFF_FB, sc + OFF_S);
  dim3 gZY(50, 64);
  k_zyg<<<gZY, 256, ZS_TOT * 4>>>(x, sc + OFF_S, sc + OFF_W + 6144, sc + OFF_YG);
  dim3 gSt(64, 16);
  k_stats<<<gSt, 256>>>((const float4*)(sc + OFF_YG));
  k_bnfinal<<<1, 64>>>(g1, b1);
  dim3 gT(30, 64);
  k_tcn<<<gT, 512>>>(sc + OFF_YG, x, sc + OFF_W + 18432, sc + OFF_Z);
  k_stats<<<gSt, 256>>>((const float4*)(sc + OFF_Z));
  k_bnfinal<<<1, 64>>>(g2, b2);
  k_addrelu<<<30000, 256>>>((const float4*)(sc + OFF_Z), (const float4*)x,
                            (float4*)out);
  if (out_size > 30720000) k_copyadj<<<8, 256>>>(adj, out);
}